// round 12
// baseline (speedup 1.0000x reference)
#include <cuda_runtime.h>
#include <cuda_fp16.h>
#include <cstdint>

// ---------------------------------------------------------------------------
// Problem constants
// ---------------------------------------------------------------------------
static constexpr int NROWS = 65536;
static constexpr int APPD  = 1024;
static constexpr int SPDIM = 512;

static constexpr int BM = 128, BN = 128, BK = 64;  // k-elements per stage

// MODE1: A fp32 (32KB) + B fp16 (16KB) per stage, x2
// MODE2: A fp16 (16KB) + B fp16 (16KB) per stage, x2
static constexpr int SMEM1 = 2 * (BM * BK * 4 + BN * BK * 2);  // 98304
static constexpr int SMEM2 = 2 * (BM * BK * 2 + BN * BK * 2);  // 65536

// ---------------------------------------------------------------------------
// Device scratch (allocation-free rule: __device__ globals)
// ---------------------------------------------------------------------------
__device__ __half g_B1h[512 * 1536];          // GEMM1 B: [n][k] = Wcat[k][n], fp16
__device__ __half g_B2h[512 * 512];           // GEMM2 B: [h][j] = W3flat[j][h], fp16
__device__ float  g_bias1[512];               // b1 + b2 (flattened c*32+s)
__device__ float  g_bias2[512];               // sum_c b3[c][:]
__device__ __half g_Hh[(size_t)65536 * 512];  // intermediate h, fp16

// ---------------------------------------------------------------------------
// Helpers (plain sm_80+ PTX only)
// ---------------------------------------------------------------------------
__device__ __forceinline__ void cp16(uint32_t smem_dst, const void* gsrc) {
    asm volatile("cp.async.cg.shared.global [%0], [%1], 16;" :: "r"(smem_dst), "l"(gsrc));
}
__device__ __forceinline__ void cp_commit() { asm volatile("cp.async.commit_group;"); }
template <int N>
__device__ __forceinline__ void cp_wait() { asm volatile("cp.async.wait_group %0;" :: "n"(N)); }

__device__ __forceinline__ uint32_t pack_h2(float lo, float hi) {
    __half2 h = __floats2half2_rn(lo, hi);
    return *reinterpret_cast<uint32_t*>(&h);
}

// m16n8k16 fp16 mma, fp32 accum.
__device__ __forceinline__ void mma16(float* d, const uint32_t* a, uint32_t b0, uint32_t b1) {
    asm volatile(
        "mma.sync.aligned.m16n8k16.row.col.f32.f16.f16.f32 "
        "{%0,%1,%2,%3}, {%4,%5,%6,%7}, {%8,%9}, {%0,%1,%2,%3};"
        : "+f"(d[0]), "+f"(d[1]), "+f"(d[2]), "+f"(d[3])
        : "r"(a[0]), "r"(a[1]), "r"(a[2]), "r"(a[3]), "r"(b0), "r"(b1));
}

// ldmatrix x4: 4 8x8 b16 tiles; lane l supplies the row address for
// tile (l>>3), row (l&7). Result: lane 4g+c of tile T gets {row g, halves 2c,2c+1}.
__device__ __forceinline__ void ldsm_x4(uint32_t* r, uint32_t addr) {
    asm volatile("ldmatrix.sync.aligned.m8n8.x4.shared.b16 {%0,%1,%2,%3}, [%4];"
                 : "=r"(r[0]), "=r"(r[1]), "=r"(r[2]), "=r"(r[3]) : "r"(addr));
}

// ---------------------------------------------------------------------------
// Prep: transpose weights -> fp16, fuse biases
// ---------------------------------------------------------------------------
__global__ void prep_kernel(const float* __restrict__ W1, const float* __restrict__ b1,
                            const float* __restrict__ W2, const float* __restrict__ b2,
                            const float* __restrict__ W3, const float* __restrict__ b3) {
    int idx = blockIdx.x * 256 + threadIdx.x;
    if (idx < 512 * 1536) {  // B1h[n][k] = Wcat[k][n];  n = c*32+s
        int n = idx / 1536, k = idx % 1536;
        int c = n >> 5, s = n & 31;
        float v = (k < APPD) ? W1[((size_t)c * APPD + k) * 32 + s]
                             : W2[((size_t)c * SPDIM + (k - APPD)) * 32 + s];
        g_B1h[idx] = __float2half_rn(v);
        return;
    }
    int i2 = idx - 512 * 1536;
    if (i2 < 512 * 512) {  // B2h[h][j] = W3flat[j][h]
        int h = i2 / 512, j = i2 % 512;
        g_B2h[i2] = __float2half_rn(W3[(size_t)j * 512 + h]);
        return;
    }
    int i3 = i2 - 512 * 512;
    if (i3 < 512) { g_bias1[i3] = b1[i3] + b2[i3]; return; }
    int i4 = i3 - 512;
    if (i4 < 512) {
        float s = 0.f;
        #pragma unroll
        for (int c = 0; c < 16; c++) s += b3[c * 512 + i4];
        g_bias2[i4] = s;
    }
}

// ---------------------------------------------------------------------------
// Tile loaders (cp.async, XOR-swizzled rows; 128 threads)
// ---------------------------------------------------------------------------
// MODE1 A: 128 rows x 64 fp32 (256B rows, swz 32*(r&7))
__device__ __forceinline__ void load_A_f32(int tid, int row0, int kt, uint32_t s_dst,
                                           const float* __restrict__ A0,
                                           const float* __restrict__ A1) {
    const float* abase; int lda;
    if (kt * BK < APPD) { abase = A0 + kt * BK; lda = APPD; }
    else                { abase = A1 + (kt * BK - APPD); lda = SPDIM; }
    #pragma unroll
    for (int i = 0; i < 16; i++) {
        int v = i * 128 + tid;
        int r = v >> 4, q = v & 15;
        cp16(s_dst + (uint32_t)(r * 256 + ((16 * q) ^ (32 * (r & 7)))),
             abase + (size_t)(row0 + r) * lda + 4 * q);
    }
}
// fp16 tile (B both modes; A in MODE2): 128 rows x 64 fp16 (128B rows)
__device__ __forceinline__ void load_h16_tile(int tid, int n0g, int kt, int ldk,
                                              uint32_t s_dst, const __half* __restrict__ B) {
    #pragma unroll
    for (int i = 0; i < 8; i++) {
        int v = i * 128 + tid;
        int r = v >> 3, q = v & 7;
        cp16(s_dst + (uint32_t)(r * 128 + ((16 * q) ^ (16 * (r & 7)))),
             B + (size_t)(n0g + r) * ldk + kt * BK + 8 * q);
    }
}

// ---------------------------------------------------------------------------
// GEMM: MODE 1: [app|sp](fp32) @ B1h -> bias+relu -> g_Hh (fp16)
//       MODE 2: g_Hh @ B2h -> bias+relu -> out (fp32)
// CTA 128x128x64, 4 warps (2x2), warp tile 64x64, fp16 HMMA fp32 accum.
// Fragment path: ldmatrix.x4 for B (and A in MODE2) + register double-buffering
// across the 4 k16 steps so LDS latency hides behind MMAs.
// ---------------------------------------------------------------------------
template <int MODE>
__global__ void __launch_bounds__(128, 2)
gemm_h(const float* __restrict__ A0, const float* __restrict__ A1,
       float* __restrict__ outp) {
    extern __shared__ char smem[];
    constexpr int ABYTES = (MODE == 1) ? BM * BK * 4 : BM * BK * 2;
    constexpr int STAGE  = ABYTES + BN * BK * 2;
    constexpr int NT     = (MODE == 1) ? (1536 / BK) : (512 / BK);

    const int tid = threadIdx.x;
    const int ncol0 = blockIdx.x * BN;   // n fastest -> A-sharing CTAs co-resident
    const int row0  = blockIdx.y * BM;
    const int lane = tid & 31, wid = tid >> 5;
    const int m0 = (wid & 1) * 64;
    const int n0 = (wid >> 1) * 64;
    const int g = lane >> 2, c = lane & 3;
    const int trow = lane & 7, tsel = lane >> 3;

    // ldmatrix per-lane address components (within a tile buffer)
    const int sw16 = 16 * trow;                    // row swizzle
    // B: x4 over nt pair p: tiles {nt=2p klo, nt=2p khi, nt=2p+1 klo, nt=2p+1 khi}
    const int b_klo = 16 * (tsel & 1);
    int browoff[4];
    #pragma unroll
    for (int p = 0; p < 4; p++)
        browoff[p] = (n0 + 16 * p + 8 * (tsel >> 1) + trow) * 128;
    // A (MODE2): x4 over one mt: tiles {rows g klo, rows g+8 klo, rows g khi, rows g+8 khi}
    const int a_klo = 16 * (tsel >> 1);
    int arowoff[4];
    #pragma unroll
    for (int mt = 0; mt < 4; mt++)
        arowoff[mt] = (m0 + 16 * mt + 8 * (tsel & 1) + trow) * 128;

    const int axor = 32 * (g & 7);                 // MODE1 fp32 A fragment swizzle

    const __half* __restrict__ Bg = (MODE == 1) ? g_B1h : g_B2h;
    const int ldb = (MODE == 1) ? 1536 : 512;

    float acc[4][8][4];
    #pragma unroll
    for (int mt = 0; mt < 4; mt++)
        #pragma unroll
        for (int nt = 0; nt < 8; nt++)
            #pragma unroll
            for (int q = 0; q < 4; q++) acc[mt][nt][q] = 0.f;

    const uint32_t sb = (uint32_t)__cvta_generic_to_shared(smem);

    // prologue: stage 0
    if (MODE == 1) load_A_f32(tid, row0, 0, sb, A0, A1);
    else           load_h16_tile(tid, row0, 0, 512, sb, g_Hh);
    load_h16_tile(tid, ncol0, 0, ldb, sb + ABYTES, Bg);
    cp_commit();

    uint32_t bf[2][16];  // [buf][4p+q]: q0=b0(2p) q1=b1(2p) q2=b0(2p+1) q3=b1(2p+1)
    uint32_t af[2][16];  // [buf][4mt+q]: a0..a3 per mt

    for (int t = 0; t < NT; t++) {
        if (t + 1 < NT) {
            uint32_t nbs = sb + ((t + 1) & 1) * STAGE;
            if (MODE == 1) load_A_f32(tid, row0, t + 1, nbs, A0, A1);
            else           load_h16_tile(tid, row0, t + 1, 512, nbs, g_Hh);
            load_h16_tile(tid, ncol0, t + 1, ldb, nbs + ABYTES, Bg);
            cp_commit();
            cp_wait<1>();
        } else {
            cp_wait<0>();
        }
        __syncthreads();  // sync1: stage t visible

        const uint32_t AsU = sb + (t & 1) * STAGE;
        const uint32_t BsU = AsU + ABYTES;
        const char* Asc = smem + (t & 1) * STAGE;   // MODE1 generic-space A reads

        // fragment loader for k16 step j into buffer d
        auto load_frags = [&](int j, uint32_t* bfd, uint32_t* afd) {
            const int boff = ((j << 5) | b_klo) ^ sw16;
            #pragma unroll
            for (int p = 0; p < 4; p++)
                ldsm_x4(bfd + 4 * p, BsU + (uint32_t)(browoff[p] + boff));
            if (MODE == 2) {
                const int aoff = ((j << 5) | a_klo) ^ sw16;
                #pragma unroll
                for (int mt = 0; mt < 4; mt++)
                    ldsm_x4(afd + 4 * mt, AsU + (uint32_t)(arowoff[mt] + aoff));
            } else {
                #pragma unroll
                for (int mt = 0; mt < 4; mt++) {
                    const char* ar0 = Asc + (m0 + 16 * mt + g) * 256;
                    const char* ar1 = ar0 + 8 * 256;
                    float2 v0 = *(const float2*)(ar0 + ((8 * c + 64 * j) ^ axor));
                    float2 v1 = *(const float2*)(ar1 + ((8 * c + 64 * j) ^ axor));
                    float2 v2 = *(const float2*)(ar0 + ((8 * c + 64 * j + 32) ^ axor));
                    float2 v3 = *(const float2*)(ar1 + ((8 * c + 64 * j + 32) ^ axor));
                    afd[4 * mt + 0] = pack_h2(v0.x, v0.y);
                    afd[4 * mt + 1] = pack_h2(v1.x, v1.y);
                    afd[4 * mt + 2] = pack_h2(v2.x, v2.y);
                    afd[4 * mt + 3] = pack_h2(v3.x, v3.y);
                }
            }
        };

        load_frags(0, bf[0], af[0]);
        #pragma unroll
        for (int j = 0; j < 4; j++) {
            const int cur = j & 1;
            if (j < 3) load_frags(j + 1, bf[cur ^ 1], af[cur ^ 1]);  // hide behind MMAs
            #pragma unroll
            for (int p = 0; p < 4; p++) {
                #pragma unroll
                for (int mt = 0; mt < 4; mt++) {
                    mma16(acc[mt][2 * p],     af[cur] + 4 * mt, bf[cur][4 * p],     bf[cur][4 * p + 1]);
                    mma16(acc[mt][2 * p + 1], af[cur] + 4 * mt, bf[cur][4 * p + 2], bf[cur][4 * p + 3]);
                }
            }
        }
        __syncthreads();  // sync2: WAR fence vs next iteration's writers
    }

    // Epilogue: bias + relu
    if (MODE == 1) {  // -> g_Hh (fp16)
        #pragma unroll
        for (int nt = 0; nt < 8; nt++) {
            const int ccol = ncol0 + n0 + 8 * nt + 2 * c;
            const float2 bv = *(const float2*)(g_bias1 + ccol);
            #pragma unroll
            for (int mt = 0; mt < 4; mt++) {
                const int r_ = row0 + m0 + 16 * mt + g;
                float x0 = fmaxf(acc[mt][nt][0] + bv.x, 0.f);
                float x1 = fmaxf(acc[mt][nt][1] + bv.y, 0.f);
                float x2 = fmaxf(acc[mt][nt][2] + bv.x, 0.f);
                float x3 = fmaxf(acc[mt][nt][3] + bv.y, 0.f);
                *(__half2*)(g_Hh + (size_t)r_ * 512 + ccol)       = __floats2half2_rn(x0, x1);
                *(__half2*)(g_Hh + (size_t)(r_ + 8) * 512 + ccol) = __floats2half2_rn(x2, x3);
            }
        }
    } else {          // -> out (fp32)
        #pragma unroll
        for (int nt = 0; nt < 8; nt++) {
            const int ccol = ncol0 + n0 + 8 * nt + 2 * c;
            const float2 bv = *(const float2*)(g_bias2 + ccol);
            #pragma unroll
            for (int mt = 0; mt < 4; mt++) {
                const int r_ = row0 + m0 + 16 * mt + g;
                float x0 = fmaxf(acc[mt][nt][0] + bv.x, 0.f);
                float x1 = fmaxf(acc[mt][nt][1] + bv.y, 0.f);
                float x2 = fmaxf(acc[mt][nt][2] + bv.x, 0.f);
                float x3 = fmaxf(acc[mt][nt][3] + bv.y, 0.f);
                *(float2*)(outp + (size_t)r_ * 512 + ccol)       = make_float2(x0, x1);
                *(float2*)(outp + (size_t)(r_ + 8) * 512 + ccol) = make_float2(x2, x3);
            }
        }
    }
}

// ---------------------------------------------------------------------------
// Launch
// ---------------------------------------------------------------------------
extern "C" void kernel_launch(void* const* d_in, const int* in_sizes, int n_in,
                              void* d_out, int out_size) {
    const float* app = (const float*)d_in[0];
    const float* sp  = (const float*)d_in[1];
    const float* W1  = (const float*)d_in[2];
    const float* b1  = (const float*)d_in[3];
    const float* W2  = (const float*)d_in[4];
    const float* b2  = (const float*)d_in[5];
    const float* W3  = (const float*)d_in[6];
    const float* b3  = (const float*)d_in[7];
    float* out = (float*)d_out;

    cudaFuncSetAttribute(gemm_h<1>, cudaFuncAttributeMaxDynamicSharedMemorySize, SMEM1);
    cudaFuncSetAttribute(gemm_h<2>, cudaFuncAttributeMaxDynamicSharedMemorySize, SMEM2);

    const int prep_elems = 512 * 1536 + 512 * 512 + 1024;
    prep_kernel<<<(prep_elems + 255) / 256, 256>>>(W1, b1, W2, b2, W3, b3);

    dim3 grid(512 / BN, NROWS / BM);  // (4, 512): n-blocks fastest -> A L2 reuse
    gemm_h<1><<<grid, 128, SMEM1>>>(app, sp, nullptr);
    gemm_h<2><<<grid, 128, SMEM2>>>(nullptr, nullptr, out);
}

// round 13
// speedup vs baseline: 1.0186x; 1.0186x over previous
#include <cuda_runtime.h>
#include <cuda_fp16.h>
#include <cstdint>

// ---------------------------------------------------------------------------
// Problem constants
// ---------------------------------------------------------------------------
static constexpr int NROWS = 65536;
static constexpr int APPD  = 1024;
static constexpr int SPDIM = 512;

static constexpr int BM = 128, BN = 128, BK = 64;  // k-elements per stage

// MODE1: 2 stages x (A fp32 32KB + B fp16 16KB) = 96KB
// MODE2: 3 stages x (A fp16 16KB + B fp16 16KB) = 96KB
static constexpr int SMEM1 = 2 * (BM * BK * 4 + BN * BK * 2);  // 98304
static constexpr int SMEM2 = 3 * (BM * BK * 2 + BN * BK * 2);  // 98304

// ---------------------------------------------------------------------------
// Device scratch (allocation-free rule: __device__ globals)
// ---------------------------------------------------------------------------
__device__ __half g_B1h[512 * 1536];          // GEMM1 B: [n][k] = Wcat[k][n], fp16
__device__ __half g_B2h[512 * 512];           // GEMM2 B: [h][j] = W3flat[j][h], fp16
__device__ float  g_bias1[512];               // b1 + b2 (flattened c*32+s)
__device__ float  g_bias2[512];               // sum_c b3[c][:]
__device__ __half g_Hh[(size_t)65536 * 512];  // intermediate h, fp16

// ---------------------------------------------------------------------------
// Helpers (plain sm_80+ PTX only)
// ---------------------------------------------------------------------------
__device__ __forceinline__ void cp16(uint32_t smem_dst, const void* gsrc) {
    asm volatile("cp.async.cg.shared.global [%0], [%1], 16;" :: "r"(smem_dst), "l"(gsrc));
}
__device__ __forceinline__ void cp_commit() { asm volatile("cp.async.commit_group;"); }
template <int N>
__device__ __forceinline__ void cp_wait() { asm volatile("cp.async.wait_group %0;" :: "n"(N)); }

__device__ __forceinline__ uint32_t pack_h2(float lo, float hi) {
    __half2 h = __floats2half2_rn(lo, hi);
    return *reinterpret_cast<uint32_t*>(&h);
}

// m16n8k16 fp16 mma, fp32 accum.
__device__ __forceinline__ void mma16(float* d, const uint32_t* a, uint32_t b0, uint32_t b1) {
    asm volatile(
        "mma.sync.aligned.m16n8k16.row.col.f32.f16.f16.f32 "
        "{%0,%1,%2,%3}, {%4,%5,%6,%7}, {%8,%9}, {%0,%1,%2,%3};"
        : "+f"(d[0]), "+f"(d[1]), "+f"(d[2]), "+f"(d[3])
        : "r"(a[0]), "r"(a[1]), "r"(a[2]), "r"(a[3]), "r"(b0), "r"(b1));
}

// ldmatrix x4: 4 8x8 b16 tiles; lane l supplies row addr for tile (l>>3), row (l&7).
__device__ __forceinline__ void ldsm_x4(uint32_t* r, uint32_t addr) {
    asm volatile("ldmatrix.sync.aligned.m8n8.x4.shared.b16 {%0,%1,%2,%3}, [%4];"
                 : "=r"(r[0]), "=r"(r[1]), "=r"(r[2]), "=r"(r[3]) : "r"(addr));
}

// ---------------------------------------------------------------------------
// Prep: transpose weights -> fp16, fuse biases
// ---------------------------------------------------------------------------
__global__ void prep_kernel(const float* __restrict__ W1, const float* __restrict__ b1,
                            const float* __restrict__ W2, const float* __restrict__ b2,
                            const float* __restrict__ W3, const float* __restrict__ b3) {
    int idx = blockIdx.x * 256 + threadIdx.x;
    if (idx < 512 * 1536) {  // B1h[n][k] = Wcat[k][n];  n = c*32+s
        int n = idx / 1536, k = idx % 1536;
        int c = n >> 5, s = n & 31;
        float v = (k < APPD) ? W1[((size_t)c * APPD + k) * 32 + s]
                             : W2[((size_t)c * SPDIM + (k - APPD)) * 32 + s];
        g_B1h[idx] = __float2half_rn(v);
        return;
    }
    int i2 = idx - 512 * 1536;
    if (i2 < 512 * 512) {  // B2h[h][j] = W3flat[j][h]
        int h = i2 / 512, j = i2 % 512;
        g_B2h[i2] = __float2half_rn(W3[(size_t)j * 512 + h]);
        return;
    }
    int i3 = i2 - 512 * 512;
    if (i3 < 512) { g_bias1[i3] = b1[i3] + b2[i3]; return; }
    int i4 = i3 - 512;
    if (i4 < 512) {
        float s = 0.f;
        #pragma unroll
        for (int c = 0; c < 16; c++) s += b3[c * 512 + i4];
        g_bias2[i4] = s;
    }
}

// ---------------------------------------------------------------------------
// Tile loaders (cp.async, XOR-swizzled rows; 128 threads)
// ---------------------------------------------------------------------------
__device__ __forceinline__ void load_A_f32(int tid, int row0, int kt, uint32_t s_dst,
                                           const float* __restrict__ A0,
                                           const float* __restrict__ A1) {
    const float* abase; int lda;
    if (kt * BK < APPD) { abase = A0 + kt * BK; lda = APPD; }
    else                { abase = A1 + (kt * BK - APPD); lda = SPDIM; }
    #pragma unroll
    for (int i = 0; i < 16; i++) {
        int v = i * 128 + tid;
        int r = v >> 4, q = v & 15;
        cp16(s_dst + (uint32_t)(r * 256 + ((16 * q) ^ (32 * (r & 7)))),
             abase + (size_t)(row0 + r) * lda + 4 * q);
    }
}
__device__ __forceinline__ void load_h16_tile(int tid, int n0g, int kt, int ldk,
                                              uint32_t s_dst, const __half* __restrict__ B) {
    #pragma unroll
    for (int i = 0; i < 8; i++) {
        int v = i * 128 + tid;
        int r = v >> 3, q = v & 7;
        cp16(s_dst + (uint32_t)(r * 128 + ((16 * q) ^ (16 * (r & 7)))),
             B + (size_t)(n0g + r) * ldk + kt * BK + 8 * q);
    }
}

// ---------------------------------------------------------------------------
// GEMM: MODE 1: [app|sp](fp32) @ B1h -> bias+relu -> g_Hh (fp16)   [2-stage]
//       MODE 2: g_Hh @ B2h -> bias+relu -> out (fp32)              [3-stage]
// CTA 128x128x64, 4 warps (2x2), warp tile 64x64, fp16 HMMA fp32 accum.
// ---------------------------------------------------------------------------
template <int MODE>
__global__ void __launch_bounds__(128, 2)
gemm_h(const float* __restrict__ A0, const float* __restrict__ A1,
       float* __restrict__ outp) {
    extern __shared__ char smem[];
    constexpr int ABYTES = (MODE == 1) ? BM * BK * 4 : BM * BK * 2;
    constexpr int STAGE  = ABYTES + BN * BK * 2;
    constexpr int NT     = (MODE == 1) ? (1536 / BK) : (512 / BK);

    const int tid = threadIdx.x;
    const int ncol0 = blockIdx.x * BN;   // n fastest -> A-sharing CTAs co-resident
    const int row0  = blockIdx.y * BM;
    const int lane = tid & 31, wid = tid >> 5;
    const int m0 = (wid & 1) * 64;
    const int n0 = (wid >> 1) * 64;
    const int g = lane >> 2, c = lane & 3;
    const int trow = lane & 7, tsel = lane >> 3;

    const int sw16 = 16 * trow;
    const int b_klo = 16 * (tsel & 1);
    int browoff[4];
    #pragma unroll
    for (int p = 0; p < 4; p++)
        browoff[p] = (n0 + 16 * p + 8 * (tsel >> 1) + trow) * 128;
    const int a_klo = 16 * (tsel >> 1);
    int arowoff[4];
    #pragma unroll
    for (int mt = 0; mt < 4; mt++)
        arowoff[mt] = (m0 + 16 * mt + 8 * (tsel & 1) + trow) * 128;

    const int axor = 32 * (g & 7);  // MODE1 fp32 A fragment swizzle

    const __half* __restrict__ Bg = (MODE == 1) ? g_B1h : g_B2h;
    const int ldb = (MODE == 1) ? 1536 : 512;

    float acc[4][8][4];
    #pragma unroll
    for (int mt = 0; mt < 4; mt++)
        #pragma unroll
        for (int nt = 0; nt < 8; nt++)
            #pragma unroll
            for (int q = 0; q < 4; q++) acc[mt][nt][q] = 0.f;

    const uint32_t sb = (uint32_t)__cvta_generic_to_shared(smem);

    // run the 4 k16-step MMA section on the stage at SMEM offset soff
    auto run_stage = [&](uint32_t soff) {
        const uint32_t AsU = sb + soff;
        const uint32_t BsU = AsU + ABYTES;
        const char* Asc = smem + soff;
        uint32_t bf[2][16], af[2][16];
        auto load_frags = [&](int j, uint32_t* bfd, uint32_t* afd) {
            const int boff = ((j << 5) | b_klo) ^ sw16;
            #pragma unroll
            for (int p = 0; p < 4; p++)
                ldsm_x4(bfd + 4 * p, BsU + (uint32_t)(browoff[p] + boff));
            if (MODE == 2) {
                const int aoff = ((j << 5) | a_klo) ^ sw16;
                #pragma unroll
                for (int mt = 0; mt < 4; mt++)
                    ldsm_x4(afd + 4 * mt, AsU + (uint32_t)(arowoff[mt] + aoff));
            } else {
                #pragma unroll
                for (int mt = 0; mt < 4; mt++) {
                    const char* ar0 = Asc + (m0 + 16 * mt + g) * 256;
                    const char* ar1 = ar0 + 8 * 256;
                    float2 v0 = *(const float2*)(ar0 + ((8 * c + 64 * j) ^ axor));
                    float2 v1 = *(const float2*)(ar1 + ((8 * c + 64 * j) ^ axor));
                    float2 v2 = *(const float2*)(ar0 + ((8 * c + 64 * j + 32) ^ axor));
                    float2 v3 = *(const float2*)(ar1 + ((8 * c + 64 * j + 32) ^ axor));
                    afd[4 * mt + 0] = pack_h2(v0.x, v0.y);
                    afd[4 * mt + 1] = pack_h2(v1.x, v1.y);
                    afd[4 * mt + 2] = pack_h2(v2.x, v2.y);
                    afd[4 * mt + 3] = pack_h2(v3.x, v3.y);
                }
            }
        };
        load_frags(0, bf[0], af[0]);
        #pragma unroll
        for (int j = 0; j < 4; j++) {
            const int cur = j & 1;
            if (j < 3) load_frags(j + 1, bf[cur ^ 1], af[cur ^ 1]);
            #pragma unroll
            for (int p = 0; p < 4; p++) {
                #pragma unroll
                for (int mt = 0; mt < 4; mt++) {
                    mma16(acc[mt][2 * p],     af[cur] + 4 * mt, bf[cur][4 * p],     bf[cur][4 * p + 1]);
                    mma16(acc[mt][2 * p + 1], af[cur] + 4 * mt, bf[cur][4 * p + 2], bf[cur][4 * p + 3]);
                }
            }
        }
    };

    if (MODE == 1) {
        // ---------------- 2-stage pipeline, 2 syncs/stage (proven) ----------
        load_A_f32(tid, row0, 0, sb, A0, A1);
        load_h16_tile(tid, ncol0, 0, ldb, sb + ABYTES, Bg);
        cp_commit();
        for (int t = 0; t < NT; t++) {
            if (t + 1 < NT) {
                uint32_t nbs = sb + ((t + 1) & 1) * STAGE;
                load_A_f32(tid, row0, t + 1, nbs, A0, A1);
                load_h16_tile(tid, ncol0, t + 1, ldb, nbs + ABYTES, Bg);
                cp_commit();
                cp_wait<1>();
            } else {
                cp_wait<0>();
            }
            __syncthreads();                 // stage t visible
            run_stage((uint32_t)((t & 1) * STAGE));
            __syncthreads();                 // WAR fence vs next iter's writers
        }
    } else {
        // ---------------- 3-stage pipeline, 1 sync/stage --------------------
        load_h16_tile(tid, row0, 0, 512, sb, g_Hh);
        load_h16_tile(tid, ncol0, 0, ldb, sb + ABYTES, Bg);
        cp_commit();
        {
            uint32_t s1 = sb + STAGE;
            load_h16_tile(tid, row0, 1, 512, s1, g_Hh);
            load_h16_tile(tid, ncol0, 1, ldb, s1 + ABYTES, Bg);
            cp_commit();
        }
        int soff = 0, nsoff = 2 * STAGE;     // stage t offset; next write offset
        for (int t = 0; t < NT; t++) {
            if (t + 1 < NT) cp_wait<1>();    // stage t done (FIFO), t+1 may pend
            else            cp_wait<0>();
            __syncthreads();                 // publish stage t; all MMA(t-1) done
            if (t + 2 < NT) {                // write buf[(t+2)%3] = buf[(t-1)%3]: safe
                load_h16_tile(tid, row0, t + 2, 512, sb + nsoff, g_Hh);
                load_h16_tile(tid, ncol0, t + 2, ldb, sb + nsoff + ABYTES, Bg);
                cp_commit();
            }
            run_stage((uint32_t)soff);
            soff  = (soff == 2 * STAGE) ? 0 : soff + STAGE;
            nsoff = (nsoff == 2 * STAGE) ? 0 : nsoff + STAGE;
        }
    }

    // Epilogue: bias + relu
    if (MODE == 1) {  // -> g_Hh (fp16)
        #pragma unroll
        for (int nt = 0; nt < 8; nt++) {
            const int ccol = ncol0 + n0 + 8 * nt + 2 * c;
            const float2 bv = *(const float2*)(g_bias1 + ccol);
            #pragma unroll
            for (int mt = 0; mt < 4; mt++) {
                const int r_ = row0 + m0 + 16 * mt + g;
                float x0 = fmaxf(acc[mt][nt][0] + bv.x, 0.f);
                float x1 = fmaxf(acc[mt][nt][1] + bv.y, 0.f);
                float x2 = fmaxf(acc[mt][nt][2] + bv.x, 0.f);
                float x3 = fmaxf(acc[mt][nt][3] + bv.y, 0.f);
                *(__half2*)(g_Hh + (size_t)r_ * 512 + ccol)       = __floats2half2_rn(x0, x1);
                *(__half2*)(g_Hh + (size_t)(r_ + 8) * 512 + ccol) = __floats2half2_rn(x2, x3);
            }
        }
    } else {          // -> out (fp32)
        #pragma unroll
        for (int nt = 0; nt < 8; nt++) {
            const int ccol = ncol0 + n0 + 8 * nt + 2 * c;
            const float2 bv = *(const float2*)(g_bias2 + ccol);
            #pragma unroll
            for (int mt = 0; mt < 4; mt++) {
                const int r_ = row0 + m0 + 16 * mt + g;
                float x0 = fmaxf(acc[mt][nt][0] + bv.x, 0.f);
                float x1 = fmaxf(acc[mt][nt][1] + bv.y, 0.f);
                float x2 = fmaxf(acc[mt][nt][2] + bv.x, 0.f);
                float x3 = fmaxf(acc[mt][nt][3] + bv.y, 0.f);
                *(float2*)(outp + (size_t)r_ * 512 + ccol)       = make_float2(x0, x1);
                *(float2*)(outp + (size_t)(r_ + 8) * 512 + ccol) = make_float2(x2, x3);
            }
        }
    }
}

// ---------------------------------------------------------------------------
// Launch
// ---------------------------------------------------------------------------
extern "C" void kernel_launch(void* const* d_in, const int* in_sizes, int n_in,
                              void* d_out, int out_size) {
    const float* app = (const float*)d_in[0];
    const float* sp  = (const float*)d_in[1];
    const float* W1  = (const float*)d_in[2];
    const float* b1  = (const float*)d_in[3];
    const float* W2  = (const float*)d_in[4];
    const float* b2  = (const float*)d_in[5];
    const float* W3  = (const float*)d_in[6];
    const float* b3  = (const float*)d_in[7];
    float* out = (float*)d_out;

    cudaFuncSetAttribute(gemm_h<1>, cudaFuncAttributeMaxDynamicSharedMemorySize, SMEM1);
    cudaFuncSetAttribute(gemm_h<2>, cudaFuncAttributeMaxDynamicSharedMemorySize, SMEM2);

    const int prep_elems = 512 * 1536 + 512 * 512 + 1024;
    prep_kernel<<<(prep_elems + 255) / 256, 256>>>(W1, b1, W2, b2, W3, b3);

    dim3 grid(512 / BN, NROWS / BM);  // (4, 512): n-blocks fastest -> A L2 reuse
    gemm_h<1><<<grid, 128, SMEM1>>>(app, sp, nullptr);
    gemm_h<2><<<grid, 128, SMEM2>>>(nullptr, nullptr, out);
}